// round 2
// baseline (speedup 1.0000x reference)
#include <cuda_runtime.h>
#include <cuda_bf16.h>

// LinAminoToAtom: out[b,g,atom,v] = sum_a x[b,n(g),a,v] * W[t(n), a, r(g)*32+atom]
// B=64, NODES=512, AMINO=64, ATOM=32, RMAX=13, NTYPES=20.
// g enumerates valid (n, r) pairs in row-major (n, r) order, r < len(type(n)).

#define NODES 512
#define BATCH 64
#define AMINO 64
#define ATOMN 32
#define RMAXJ 416   // RMAX*ATOM = 13*32
#define XSTR  193   // x smem row stride (odd -> conflict-free)
#define OSTR  97    // out smem row stride (odd -> conflict-free)

__constant__ int c_reslen[20] = {4,10,7,7,5,8,8,3,9,7,7,8,7,10,6,5,6,13,11,6};

__device__ int d_type[NODES];
__device__ int d_len[NODES];
__device__ int d_gbase[NODES];

// ---------- setup: dtype-robust type read + per-node len + exclusive prefix ----------
// type_ids may be int32 or int64 (JAX x64-disabled silently downcasts). Detect:
// viewing as int32, int64 data shows [v,0,v,0,...] with v<20. Probe 256 pairs
// (<=512 int32 words, in-bounds for both widths).
__global__ void setup_kernel(const void* __restrict__ tids_raw) {
    const int* s32 = (const int*)tids_raw;
    __shared__ int s[NODES];
    __shared__ int flag64;
    int n = threadIdx.x;
    if (n == 0) flag64 = 1;
    __syncthreads();
    if (n < 256) {
        int lo = s32[2 * n], hi = s32[2 * n + 1];
        if (hi != 0 || (unsigned)lo >= 20u) atomicAnd(&flag64, 0);
    }
    __syncthreads();
    int t = flag64 ? s32[2 * n] : s32[n];
    int l = c_reslen[t];
    d_type[n] = t;
    d_len[n]  = l;
    s[n] = l;
    __syncthreads();
    // Hillis-Steele inclusive scan over 512
    for (int off = 1; off < NODES; off <<= 1) {
        int v = (n >= off) ? s[n - off] : 0;
        __syncthreads();
        s[n] += v;
        __syncthreads();
    }
    d_gbase[n] = s[n] - l;  // exclusive prefix
}

// ---------- f32x2 helpers ----------
__device__ __forceinline__ unsigned long long dup2(float v) {
    unsigned long long r;
    asm("mov.b64 %0, {%1, %1};" : "=l"(r) : "f"(v));
    return r;
}
__device__ __forceinline__ void fma2(unsigned long long& d, unsigned long long a,
                                     unsigned long long b) {
    asm("fma.rn.f32x2 %0, %1, %2, %0;" : "+l"(d) : "l"(a), "l"(b));
}

// dynamic smem layout (floats):
//   xs : BATCH*XSTR      = 12352
//   ws : AMINO*ATOMN     = 2048
//   os : BATCH*OSTR      = 6208
#define XS_F (BATCH * XSTR)
#define WS_F (AMINO * ATOMN)
#define OS_F (BATCH * OSTR)
#define SMEM_BYTES ((XS_F + WS_F + OS_F) * 4)

__global__ void __launch_bounds__(256, 2)
lin_amino_kernel(const float* __restrict__ x, const float* __restrict__ W,
                 float* __restrict__ out, int G) {
    extern __shared__ float smem[];
    float* xs = smem;
    float* ws = smem + XS_F;
    float* os = smem + XS_F + WS_F;

    const int n   = blockIdx.x;
    const int tid = threadIdx.x;
    const int t   = d_type[n];
    const int len = d_len[n];
    const int gb  = d_gbase[n];

    // ---- stage x[:, n, :, :] : BATCH rows of 192 floats, padded stride XSTR ----
    for (int f = tid; f < BATCH * 48; f += 256) {
        int b = f / 48, c4 = f % 48;
        float4 v = *reinterpret_cast<const float4*>(
            x + ((size_t)b * NODES + n) * 192 + c4 * 4);
        float* dst = xs + b * XSTR + c4 * 4;
        dst[0] = v.x; dst[1] = v.y; dst[2] = v.z; dst[3] = v.w;
    }

    const int ag = tid >> 6;   // atom group 0..3 (8 atoms each)
    const int b  = tid & 63;   // batch lane
    const float* xr = xs + b * XSTR;
    const float* wp = ws + ag * 8;
    const float* Wt = W + (size_t)t * AMINO * RMAXJ;

    for (int r = 0; r < len; ++r) {
        __syncthreads();  // ws/os safe to overwrite (also covers x staging at r=0)

        // ---- stage W[t, :, r*32 .. r*32+32) -> ws[a*32 + c] ----
        {
            const float* Wr = Wt + r * ATOMN;
            for (int i = tid; i < WS_F; i += 256) {
                int a = i >> 5, c = i & 31;
                ws[i] = Wr[(size_t)a * RMAXJ + c];
            }
        }
        __syncthreads();

        // ---- compute: 8 atoms x 3 v for one batch, 12 f32x2 accumulators ----
        unsigned long long acc[12];
#pragma unroll
        for (int i = 0; i < 12; ++i) acc[i] = 0ull;

#pragma unroll 16
        for (int a = 0; a < AMINO; ++a) {
            union { float4 f; unsigned long long u[2]; } w0, w1;
            w0.f = *reinterpret_cast<const float4*>(wp + a * ATOMN);
            w1.f = *reinterpret_cast<const float4*>(wp + a * ATOMN + 4);
            float x0 = xr[a * 3 + 0];
            float x1 = xr[a * 3 + 1];
            float x2 = xr[a * 3 + 2];
            unsigned long long d0 = dup2(x0), d1 = dup2(x1), d2 = dup2(x2);
            fma2(acc[0],  w0.u[0], d0); fma2(acc[1],  w0.u[0], d1); fma2(acc[2],  w0.u[0], d2);
            fma2(acc[3],  w0.u[1], d0); fma2(acc[4],  w0.u[1], d1); fma2(acc[5],  w0.u[1], d2);
            fma2(acc[6],  w1.u[0], d0); fma2(acc[7],  w1.u[0], d1); fma2(acc[8],  w1.u[0], d2);
            fma2(acc[9],  w1.u[1], d0); fma2(acc[10], w1.u[1], d1); fma2(acc[11], w1.u[1], d2);
        }

        // ---- scatter to smem out row (stride OSTR keeps lanes conflict-free) ----
        {
            float* ob = os + b * OSTR + ag * 24;  // 8 atoms * 3 v = 24 floats
#pragma unroll
            for (int p = 0; p < 4; ++p) {
#pragma unroll
                for (int v = 0; v < 3; ++v) {
                    union { unsigned long long u; float f[2]; } z;
                    z.u = acc[p * 3 + v];
                    ob[(2 * p) * 3 + v]     = z.f[0];
                    ob[(2 * p + 1) * 3 + v] = z.f[1];
                }
            }
        }
        __syncthreads();

        // ---- coalesced store: row (b, gb+r) = 96 contiguous floats ----
        for (int f4 = tid; f4 < BATCH * 24; f4 += 256) {
            int b2 = f4 / 24, c4 = f4 % 24;
            const float* s = os + b2 * OSTR + c4 * 4;
            float4 v;
            v.x = s[0]; v.y = s[1]; v.z = s[2]; v.w = s[3];
            *reinterpret_cast<float4*>(
                out + ((size_t)b2 * G + gb + r) * 96 + c4 * 4) = v;
        }
    }
}

extern "C" void kernel_launch(void* const* d_in, const int* in_sizes, int n_in,
                              void* d_out, int out_size) {
    const float* x    = (const float*)d_in[0];
    const float* W    = (const float*)d_in[1];
    const void*  tids = d_in[2];
    float*       out  = (float*)d_out;

    int G = in_sizes[3];  // gather_idx element count == number of valid rows

    cudaFuncSetAttribute(lin_amino_kernel,
                         cudaFuncAttributeMaxDynamicSharedMemorySize, SMEM_BYTES);

    setup_kernel<<<1, NODES>>>(tids);
    lin_amino_kernel<<<NODES, 256, SMEM_BYTES>>>(x, W, out, G);
}

// round 3
// speedup vs baseline: 1.0397x; 1.0397x over previous
#include <cuda_runtime.h>
#include <cuda_bf16.h>

// LinAminoToAtom: out[b,g,atom,v] = sum_a x[b,n(g),a,v] * W[t(n), a, r(g)*32+atom]
// B=64, NODES=512, AMINO=64, ATOM=32, RMAX=13, NTYPES=20.
// One block per valid residue g (uniform work, perfect balance).

#define NODES 512
#define BATCH 64
#define AMINO 64
#define ATOMN 32
#define RMAXJ 416   // RMAX*ATOM = 13*32
#define XSTR  193   // x smem row stride (odd -> conflict-free)
#define OSTR  97    // out smem row stride (odd -> conflict-free)
#define MAXG  (NODES * 13)

__constant__ int c_reslen[20] = {4,10,7,7,5,8,8,3,9,7,7,8,7,10,6,5,6,13,11,6};

// packed per-residue metadata: n | (r<<9) | (t<<13)
__device__ int d_gmeta[MAXG];

// ---------- setup: dtype-robust type read + prefix scan + per-g metadata ----------
// type_ids may be int32 or int64 (JAX x64-disabled downcasts). Viewed as int32,
// int64 data is [v,0,v,0,...] with v<20; probe 256 pairs (in-bounds either way).
__global__ void setup_kernel(const void* __restrict__ tids_raw) {
    const int* s32 = (const int*)tids_raw;
    __shared__ int wsum[16];
    __shared__ int flag64;
    int n = threadIdx.x;
    if (n == 0) flag64 = 1;
    __syncthreads();
    if (n < 256) {
        int lo = s32[2 * n], hi = s32[2 * n + 1];
        if (hi != 0 || (unsigned)lo >= 20u) atomicAnd(&flag64, 0);
    }
    __syncthreads();
    int t = flag64 ? s32[2 * n] : s32[n];
    int l = c_reslen[t];

    int lane = n & 31, wid = n >> 5;
    // warp inclusive scan of lengths
    int v = l;
#pragma unroll
    for (int off = 1; off < 32; off <<= 1) {
        int u = __shfl_up_sync(0xffffffffu, v, off);
        if (lane >= off) v += u;
    }
    if (lane == 31) wsum[wid] = v;
    __syncthreads();
    if (wid == 0 && lane < 16) {
        int s = wsum[lane];
#pragma unroll
        for (int off = 1; off < 16; off <<= 1) {
            int u = __shfl_up_sync(0x0000ffffu, s, off);
            if (lane >= off) s += u;
        }
        wsum[lane] = s;
    }
    __syncthreads();
    int gb = v - l + (wid > 0 ? wsum[wid - 1] : 0);  // exclusive prefix
    for (int r = 0; r < l; ++r)
        d_gmeta[gb + r] = n | (r << 9) | (t << 13);
}

// ---------- f32x2 helpers ----------
__device__ __forceinline__ unsigned long long dup2(float v) {
    unsigned long long r;
    asm("mov.b64 %0, {%1, %1};" : "=l"(r) : "f"(v));
    return r;
}
__device__ __forceinline__ void fma2(unsigned long long& d, unsigned long long a,
                                     unsigned long long b) {
    asm("fma.rn.f32x2 %0, %1, %2, %0;" : "+l"(d) : "l"(a), "l"(b));
}

// dynamic smem (floats):
//   xs : BATCH*XSTR = 12352
//   sh : max(ws 2048, os 6208) = 6208   (ws during compute, os for store)
#define XS_F (BATCH * XSTR)
#define SH_F (BATCH * OSTR)
#define SMEM_BYTES ((XS_F + SH_F) * 4)

__global__ void __launch_bounds__(256, 3)
lin_amino_kernel(const float* __restrict__ x, const float* __restrict__ W,
                 float* __restrict__ out, int G) {
    extern __shared__ float smem[];
    float* xs = smem;
    float* ws = smem + XS_F;   // also reused as os after compute
    float* os = smem + XS_F;

    const int g   = blockIdx.x;
    const int tid = threadIdx.x;
    const int m   = d_gmeta[g];
    const int n   = m & 511;
    const int r   = (m >> 9) & 15;
    const int t   = m >> 13;

    // ---- stage x[:, n, :, :] : 64 rows of 192 floats, padded stride XSTR ----
    for (int f = tid; f < BATCH * 48; f += 256) {
        int b = f / 48, c4 = f % 48;
        float4 v = *reinterpret_cast<const float4*>(
            x + ((size_t)b * NODES + n) * 192 + c4 * 4);
        float* dst = xs + b * XSTR + c4 * 4;
        dst[0] = v.x; dst[1] = v.y; dst[2] = v.z; dst[3] = v.w;
    }

    // ---- stage W[t, :, r*32 .. r*32+32) -> ws[a*32 + c] : 512 float4 ----
    {
        const float* Wr = W + (size_t)t * AMINO * RMAXJ + r * ATOMN;
        for (int i = tid; i < 512; i += 256) {
            int a = i >> 3, c4 = i & 7;
            float4 v = *reinterpret_cast<const float4*>(Wr + (size_t)a * RMAXJ + c4 * 4);
            float* dst = ws + a * ATOMN + c4 * 4;
            dst[0] = v.x; dst[1] = v.y; dst[2] = v.z; dst[3] = v.w;
        }
    }
    __syncthreads();

    const int ag = tid >> 6;   // atom group 0..3 (8 atoms each)
    const int b  = tid & 63;   // batch lane
    const float* xr = xs + b * XSTR;
    const float* wp = ws + ag * 8;

    // ---- compute: 8 atoms x 3 v for one batch, 12 f32x2 accumulators ----
    unsigned long long acc[12];
#pragma unroll
    for (int i = 0; i < 12; ++i) acc[i] = 0ull;

#pragma unroll 16
    for (int a = 0; a < AMINO; ++a) {
        union { float4 f; unsigned long long u[2]; } w0, w1;
        w0.f = *reinterpret_cast<const float4*>(wp + a * ATOMN);
        w1.f = *reinterpret_cast<const float4*>(wp + a * ATOMN + 4);
        float x0 = xr[a * 3 + 0];
        float x1 = xr[a * 3 + 1];
        float x2 = xr[a * 3 + 2];
        unsigned long long d0 = dup2(x0), d1 = dup2(x1), d2 = dup2(x2);
        fma2(acc[0],  w0.u[0], d0); fma2(acc[1],  w0.u[0], d1); fma2(acc[2],  w0.u[0], d2);
        fma2(acc[3],  w0.u[1], d0); fma2(acc[4],  w0.u[1], d1); fma2(acc[5],  w0.u[1], d2);
        fma2(acc[6],  w1.u[0], d0); fma2(acc[7],  w1.u[0], d1); fma2(acc[8],  w1.u[0], d2);
        fma2(acc[9],  w1.u[1], d0); fma2(acc[10], w1.u[1], d1); fma2(acc[11], w1.u[1], d2);
    }
    __syncthreads();  // ws is dead; os may now overwrite it

    // ---- scatter to smem out rows (stride OSTR conflict-free) ----
    {
        float* ob = os + b * OSTR + ag * 24;  // 8 atoms * 3 v = 24 floats
#pragma unroll
        for (int p = 0; p < 4; ++p) {
#pragma unroll
            for (int v = 0; v < 3; ++v) {
                union { unsigned long long u; float f[2]; } z;
                z.u = acc[p * 3 + v];
                ob[(2 * p) * 3 + v]     = z.f[0];
                ob[(2 * p + 1) * 3 + v] = z.f[1];
            }
        }
    }
    __syncthreads();

    // ---- coalesced store: row (b, g) = 96 contiguous floats ----
    for (int f4 = tid; f4 < BATCH * 24; f4 += 256) {
        int b2 = f4 / 24, c4 = f4 % 24;
        const float* s = os + b2 * OSTR + c4 * 4;
        float4 v;
        v.x = s[0]; v.y = s[1]; v.z = s[2]; v.w = s[3];
        *reinterpret_cast<float4*>(
            out + ((size_t)b2 * G + g) * 96 + c4 * 4) = v;
    }
}

extern "C" void kernel_launch(void* const* d_in, const int* in_sizes, int n_in,
                              void* d_out, int out_size) {
    const float* x    = (const float*)d_in[0];
    const float* W    = (const float*)d_in[1];
    const void*  tids = d_in[2];
    float*       out  = (float*)d_out;

    int G = in_sizes[3];  // number of valid residues (gather_idx length)

    cudaFuncSetAttribute(lin_amino_kernel,
                         cudaFuncAttributeMaxDynamicSharedMemorySize, SMEM_BYTES);

    setup_kernel<<<1, NODES>>>(tids);
    lin_amino_kernel<<<G, 256, SMEM_BYTES>>>(x, W, out, G);
}

// round 4
// speedup vs baseline: 1.2258x; 1.1790x over previous
#include <cuda_runtime.h>
#include <cuda_bf16.h>

// LinAminoToAtom: out[b,g,atom,v] = sum_a x[b,n(g),a,v] * W[t(n), a, r(g)*32+atom]
// B=64, NODES=512, AMINO=64, ATOM=32, RMAX=13, NTYPES=20.
// One block per PAIR of residues of one node: x smem loads feed 2x the FFMA2.

#define NODES 512
#define BATCH 64
#define AMINO 64
#define ATOMN 32
#define RMAXJ 416   // RMAX*ATOM = 13*32
#define XSTR  193   // x smem row stride (odd -> conflict-free scalar LDS)
#define OSTR  97    // out smem row stride (odd -> conflict-free)
#define MAXP  (NODES * 7)   // max residue pairs (ceil(13/2) = 7)

__constant__ int c_reslen[20] = {4,10,7,7,5,8,8,3,9,7,7,8,7,10,6,5,6,13,11,6};

// packed pair metadata: n(9) | r0(4) | t(5) | cnt2(1) | g(13)
__device__ int d_pmeta[MAXP];
__device__ int d_pcount;

// ---------- setup: dtype-robust type read + dual prefix scan + pair metadata ----
// type_ids may be int32 or int64 (JAX x64-disabled downcasts). Viewed as int32,
// int64 data is [v,0,v,0,...] with v<20; probe 256 pairs (in-bounds either way).
__global__ void setup_kernel(const void* __restrict__ tids_raw) {
    const int* s32 = (const int*)tids_raw;
    __shared__ int wsumL[16], wsumP[16];
    __shared__ int flag64;
    int n = threadIdx.x;
    if (n == 0) flag64 = 1;
    __syncthreads();
    if (n < 256) {
        int lo = s32[2 * n], hi = s32[2 * n + 1];
        if (hi != 0 || (unsigned)lo >= 20u) atomicAnd(&flag64, 0);
    }
    __syncthreads();
    int t = flag64 ? s32[2 * n] : s32[n];
    int l = c_reslen[t];
    int p = (l + 1) >> 1;

    int lane = n & 31, wid = n >> 5;
    int vl = l, vp = p;
#pragma unroll
    for (int off = 1; off < 32; off <<= 1) {
        int ul = __shfl_up_sync(0xffffffffu, vl, off);
        int up = __shfl_up_sync(0xffffffffu, vp, off);
        if (lane >= off) { vl += ul; vp += up; }
    }
    if (lane == 31) { wsumL[wid] = vl; wsumP[wid] = vp; }
    __syncthreads();
    if (wid == 0 && lane < 16) {
        int sl = wsumL[lane], sp = wsumP[lane];
#pragma unroll
        for (int off = 1; off < 16; off <<= 1) {
            int ul = __shfl_up_sync(0x0000ffffu, sl, off);
            int up = __shfl_up_sync(0x0000ffffu, sp, off);
            if (lane >= off) { sl += ul; sp += up; }
        }
        wsumL[lane] = sl; wsumP[lane] = sp;
        if (lane == 15) d_pcount = sp;
    }
    __syncthreads();
    int gb = vl - l + (wid > 0 ? wsumL[wid - 1] : 0);  // exclusive prefix of lens
    int pb = vp - p + (wid > 0 ? wsumP[wid - 1] : 0);  // exclusive prefix of pairs
    for (int k = 0; k < p; ++k) {
        int r0 = 2 * k;
        int cnt2 = (r0 + 1 < l) ? 1 : 0;
        d_pmeta[pb + k] = n | (r0 << 9) | (t << 13) | (cnt2 << 18) | ((gb + r0) << 19);
    }
}

// ---------- f32x2 helpers ----------
__device__ __forceinline__ unsigned long long dup2(float v) {
    unsigned long long r;
    asm("mov.b64 %0, {%1, %1};" : "=l"(r) : "f"(v));
    return r;
}
__device__ __forceinline__ void fma2(unsigned long long& d, unsigned long long a,
                                     unsigned long long b) {
    asm("fma.rn.f32x2 %0, %1, %2, %0;" : "+l"(d) : "l"(a), "l"(b));
}

// dynamic smem (floats):
//   xs : BATCH*XSTR = 12352
//   sh : max(ws 2*2048=4096, os 6208) = 6208  (ws during compute, os per-residue store)
#define XS_F (BATCH * XSTR)
#define SH_F (BATCH * OSTR)
#define SMEM_BYTES ((XS_F + SH_F) * 4)

__global__ void __launch_bounds__(256, 3)
lin_amino_kernel(const float* __restrict__ x, const float* __restrict__ W,
                 float* __restrict__ out, int G) {
    extern __shared__ float smem[];
    float* xs = smem;
    float* ws = smem + XS_F;   // 2 x 2048 floats during compute
    float* os = smem + XS_F;   // reused for store staging

    const int pid = blockIdx.x;
    if (pid >= d_pcount) return;
    const int tid = threadIdx.x;
    const int m   = d_pmeta[pid];
    const int n   = m & 511;
    const int r0  = (m >> 9) & 15;
    const int t   = (m >> 13) & 31;
    const int cnt2= (m >> 18) & 1;
    const int g   = (m >> 19);
    const int r1  = cnt2 ? (r0 + 1) : r0;   // clamp: valid row, result discarded

    // ---- stage x[:, n, :, :] : 64 rows of 192 floats, padded stride XSTR ----
    for (int f = tid; f < BATCH * 48; f += 256) {
        int b = f / 48, c4 = f % 48;
        float4 v = *reinterpret_cast<const float4*>(
            x + ((size_t)b * NODES + n) * 192 + c4 * 4);
        float* dst = xs + b * XSTR + c4 * 4;
        dst[0] = v.x; dst[1] = v.y; dst[2] = v.z; dst[3] = v.w;
    }

    // ---- stage W tiles for both residues: ws[res*2048 + a*32 + c] ----
    {
        const float* Wt = W + (size_t)t * AMINO * RMAXJ;
        for (int i = tid; i < 1024; i += 256) {     // 1024 float4
            int res = i >> 9, j = i & 511;
            int a = j >> 3, c4 = j & 7;
            int rr = res ? r1 : r0;
            float4 v = *reinterpret_cast<const float4*>(
                Wt + (size_t)a * RMAXJ + rr * ATOMN + c4 * 4);
            float* dst = ws + res * 2048 + a * ATOMN + c4 * 4;
            dst[0] = v.x; dst[1] = v.y; dst[2] = v.z; dst[3] = v.w;
        }
    }
    __syncthreads();

    const int ag = tid >> 6;   // atom group 0..3 (8 atoms each)
    const int b  = tid & 63;   // batch lane
    const float* xr  = xs + b * XSTR;
    const float* wp0 = ws + ag * 8;
    const float* wp1 = ws + 2048 + ag * 8;

    // ---- compute: 2 residues x 8 atoms x 3 v, 24 f32x2 accumulators ----
    unsigned long long acc[24];
#pragma unroll
    for (int i = 0; i < 24; ++i) acc[i] = 0ull;

#pragma unroll 8
    for (int a = 0; a < AMINO; ++a) {
        union { float4 f; unsigned long long u[2]; } w00, w01, w10, w11;
        w00.f = *reinterpret_cast<const float4*>(wp0 + a * ATOMN);
        w01.f = *reinterpret_cast<const float4*>(wp0 + a * ATOMN + 4);
        w10.f = *reinterpret_cast<const float4*>(wp1 + a * ATOMN);
        w11.f = *reinterpret_cast<const float4*>(wp1 + a * ATOMN + 4);
        float x0 = xr[a * 3 + 0];
        float x1 = xr[a * 3 + 1];
        float x2 = xr[a * 3 + 2];
        unsigned long long d0 = dup2(x0), d1 = dup2(x1), d2 = dup2(x2);
        fma2(acc[0],  w00.u[0], d0); fma2(acc[1],  w00.u[0], d1); fma2(acc[2],  w00.u[0], d2);
        fma2(acc[3],  w00.u[1], d0); fma2(acc[4],  w00.u[1], d1); fma2(acc[5],  w00.u[1], d2);
        fma2(acc[6],  w01.u[0], d0); fma2(acc[7],  w01.u[0], d1); fma2(acc[8],  w01.u[0], d2);
        fma2(acc[9],  w01.u[1], d0); fma2(acc[10], w01.u[1], d1); fma2(acc[11], w01.u[1], d2);
        fma2(acc[12], w10.u[0], d0); fma2(acc[13], w10.u[0], d1); fma2(acc[14], w10.u[0], d2);
        fma2(acc[15], w10.u[1], d0); fma2(acc[16], w10.u[1], d1); fma2(acc[17], w10.u[1], d2);
        fma2(acc[18], w11.u[0], d0); fma2(acc[19], w11.u[0], d1); fma2(acc[20], w11.u[0], d2);
        fma2(acc[21], w11.u[1], d0); fma2(acc[22], w11.u[1], d1); fma2(acc[23], w11.u[1], d2);
    }

    // ---- phased store: for each residue, scatter to smem then coalesced STG ----
    const int nres = 1 + cnt2;
    for (int res = 0; res < nres; ++res) {
        __syncthreads();   // os free (ws dead after compute / prev store done)
        {
            float* ob = os + b * OSTR + ag * 24;
            const unsigned long long* ar = acc + res * 12;
#pragma unroll
            for (int p = 0; p < 4; ++p) {
#pragma unroll
                for (int v = 0; v < 3; ++v) {
                    union { unsigned long long u; float f[2]; } z;
                    z.u = ar[p * 3 + v];
                    ob[(2 * p) * 3 + v]     = z.f[0];
                    ob[(2 * p + 1) * 3 + v] = z.f[1];
                }
            }
        }
        __syncthreads();
        for (int f4 = tid; f4 < BATCH * 24; f4 += 256) {
            int b2 = f4 / 24, c4 = f4 % 24;
            const float* s = os + b2 * OSTR + c4 * 4;
            float4 v;
            v.x = s[0]; v.y = s[1]; v.z = s[2]; v.w = s[3];
            *reinterpret_cast<float4*>(
                out + ((size_t)b2 * G + g + res) * 96 + c4 * 4) = v;
        }
    }
}

extern "C" void kernel_launch(void* const* d_in, const int* in_sizes, int n_in,
                              void* d_out, int out_size) {
    const float* x    = (const float*)d_in[0];
    const float* W    = (const float*)d_in[1];
    const void*  tids = d_in[2];
    float*       out  = (float*)d_out;

    int G = in_sizes[3];  // number of valid residues (gather_idx length)

    cudaFuncSetAttribute(lin_amino_kernel,
                         cudaFuncAttributeMaxDynamicSharedMemorySize, SMEM_BYTES);

    setup_kernel<<<1, NODES>>>(tids);
    lin_amino_kernel<<<MAXP, 256, SMEM_BYTES>>>(x, W, out, G);
}